// round 17
// baseline (speedup 1.0000x reference)
#include <cuda_runtime.h>
#include <math.h>

#define NN   50000
#define EE   800000
#define GG   64
#define LB   512         // logit reduction blocks
#define SCAN_T 1024
#define CH   49          // ceil(NN / SCAN_T)

typedef unsigned long long ull;
typedef unsigned int uint;

// ---------------- scratch (device globals: no allocs allowed) ----------------
__device__ float g_bufA[NN * 128];   // xw (fp32)
__device__ float g_bufB[NN * 128];   // h
__device__ float g_bufC[NN * 128];   // conv accumulator, then attention agg
__device__ float g_dinv[NN];
__device__ int   g_ccount[NN];       // in-degree (col)
__device__ int   g_ccur[NN];         // running fill positions
__device__ int   g_srcS[EE];         // edges sorted by dst: source node
__device__ int   g_dstS[EE];         //                      dest node
__device__ float g_nrmS[EE];         //                      dinv[r]*dinv[c]
__device__ float g_ar[NN];
__device__ float g_ac[NN];
__device__ float g_attsum[NN];
__device__ float g_blockm[LB];
__device__ float g_blocks[LB];
__device__ float g_gmax;
__device__ float g_invsum;
__device__ float g_pooled[GG * 128];
__device__ float g_cnt[GG];
// B-fragment tables in MMA lane order: [nt][ks][lane] = {b0hi,b1hi,b0lo,b1lo}
__device__ uint4 g_wf1[16 * 8 * 32];   // W1  (K=128: 8 ks)
__device__ uint4 g_wf2[16 * 8 * 32];   // W2
__device__ uint4 g_wfa[16 * 8 * 32];   // We2
__device__ uint4 g_wfe[16 * 2 * 32];   // We1 (K=32: 2 ks)

__device__ __forceinline__ float eluf(float x) {
    return x > 0.f ? x : (expf(x) - 1.f);
}
__device__ __forceinline__ void red4(float* addr, float a, float b, float c, float d) {
    asm volatile("red.global.add.v4.f32 [%0], {%1,%2,%3,%4};"
                 :: "l"(addr), "f"(a), "f"(b), "f"(c), "f"(d) : "memory");
}
__device__ __forceinline__ void red1(float* addr, float a) {
    asm volatile("red.global.add.f32 [%0], %1;" :: "l"(addr), "f"(a) : "memory");
}
// packed bf16x2: first arg -> low half, second -> high half
__device__ __forceinline__ uint bf2(float lo, float hi) {
    uint r; asm("cvt.rn.bf16x2.f32 %0, %1, %2;" : "=r"(r) : "f"(hi), "f"(lo));
    return r;
}
// split (x,y) fp32 pair into packed bf16 hi + residual lo
__device__ __forceinline__ void split2f(float x, float y, uint& hi, uint& lo) {
    hi = bf2(x, y);
    float hx = __uint_as_float(hi << 16);
    float hy = __uint_as_float(hi & 0xffff0000u);
    lo = bf2(x - hx, y - hy);
}
// m16n8k16 bf16 MMA, fp32 accumulate (accumulates into d)
__device__ __forceinline__ void mma_bf16(float* d, const uint* a, uint b0, uint b1) {
    asm("mma.sync.aligned.m16n8k16.row.col.f32.bf16.bf16.f32 "
        "{%0,%1,%2,%3}, {%4,%5,%6,%7}, {%8,%9}, {%0,%1,%2,%3};"
        : "+f"(d[0]), "+f"(d[1]), "+f"(d[2]), "+f"(d[3])
        : "r"(a[0]), "r"(a[1]), "r"(a[2]), "r"(a[3]), "r"(b0), "r"(b1));
}

// ---------------- init (+ weight fragment tables) ----------------
__global__ void k_init(const float* __restrict__ W1, const float* __restrict__ W2,
                       const float* __restrict__ We2, const float* __restrict__ We1) {
    int i = blockIdx.x * blockDim.x + threadIdx.x;
    if (i < NN)       { g_ccount[i] = 0; g_attsum[i] = 0.0f; }
    if (i < GG * 128) g_pooled[i] = 0.0f;
    if (i < GG)       g_cnt[i]   = 0.0f;
    // node-weight tables (K=128)
    if (i < 3 * 4096) {
        int w = i >> 12, j = i & 4095;
        int nt = j >> 8, r = j & 255;
        int ks = r >> 5, lane = r & 31;
        int quad = lane >> 2, tig = lane & 3;
        int n = nt * 8 + quad;
        int kp0 = ks * 8 + tig;
        int kp1 = kp0 + 4;
        const float* W = (w == 0) ? W1 : (w == 1) ? W2 : We2;
        uint hi0, lo0, hi1, lo1;
        split2f(W[(2 * kp0) * 128 + n], W[(2 * kp0 + 1) * 128 + n], hi0, lo0);
        split2f(W[(2 * kp1) * 128 + n], W[(2 * kp1 + 1) * 128 + n], hi1, lo1);
        uint4* dst = (w == 0) ? g_wf1 : (w == 1) ? g_wf2 : g_wfa;
        dst[j] = make_uint4(hi0, hi1, lo0, lo1);
    }
    // edge-weight table We1 (K=32: 2 ks)
    if (i < 1024) {
        int nt = i >> 6, r = i & 63;
        int ks = r >> 5, lane = r & 31;
        int quad = lane >> 2, tig = lane & 3;
        int n = nt * 8 + quad;
        int kp0 = ks * 8 + tig;
        int kp1 = kp0 + 4;
        uint hi0, lo0, hi1, lo1;
        split2f(We1[(2 * kp0) * 128 + n], We1[(2 * kp0 + 1) * 128 + n], hi0, lo0);
        split2f(We1[(2 * kp1) * 128 + n], We1[(2 * kp1 + 1) * 128 + n], hi1, lo1);
        g_wfe[i] = make_uint4(hi0, hi1, lo0, lo1);
    }
}

// column (destination) degree count
__global__ void k_count(const int* __restrict__ ei) {
    int e = blockIdx.x * blockDim.x + threadIdx.x;
    if (e < EE) atomicAdd(&g_ccount[ei[EE + e]], 1);
}

// single-block exclusive scan of column counts -> fill positions; also
// dinv = rsqrt(indeg + 2)  (double self-loop)
__global__ void __launch_bounds__(SCAN_T) k_scan() {
    __shared__ int sm[SCAN_T];
    int t = threadIdx.x;
    int base = t * CH;
    int s = 0;
    for (int i = 0; i < CH; i++) {
        int idx = base + i;
        if (idx < NN) s += g_ccount[idx];
    }
    sm[t] = s;
    __syncthreads();
    for (int o = 1; o < SCAN_T; o <<= 1) {
        int v = (t >= o) ? sm[t - o] : 0;
        __syncthreads();
        sm[t] += v;
        __syncthreads();
    }
    int run = (t > 0) ? sm[t - 1] : 0;
    for (int i = 0; i < CH; i++) {
        int idx = base + i;
        if (idx < NN) {
            int c = g_ccount[idx];
            g_ccur[idx] = run;
            g_dinv[idx] = rsqrtf((float)(c + 2));
            run += c;
        }
    }
}

// fill dst-sorted edge arrays (src, dst, nrm)
__global__ void k_fill(const int* __restrict__ ei) {
    int e = blockIdx.x * blockDim.x + threadIdx.x;
    if (e >= EE) return;
    int r = ei[e], c = ei[EE + e];
    int p = atomicAdd(&g_ccur[c], 1);
    g_srcS[p] = r;
    g_dstS[p] = c;
    g_nrmS[p] = __ldg(&g_dinv[r]) * __ldg(&g_dinv[c]);
}

// batch counts with per-thread run accumulation (batch is sorted)
__global__ void k_cnt(const int* __restrict__ batch) {
    int base = (blockIdx.x * blockDim.x + threadIdx.x) * 8;
    if (base >= NN) return;
    int cur = batch[base];
    float a = 0.f;
    for (int t = 0; t < 8; t++) {
        int n = base + t;
        if (n >= NN) break;
        int g = batch[n];
        if (g != cur) { red1(&g_cnt[cur], a); cur = g; a = 0.f; }
        a += 1.f;
    }
    red1(&g_cnt[cur], a);
}

// ---------------- tensor-core GEMM core (node GEMMs, K=128) ----------------
// A-loads software-pipelined: ks+1 loads issued before ks's MMA burst.
__device__ __forceinline__ void mma_core(const float* __restrict__ A,
                                         const uint4* __restrict__ Wf_half,
                                         int r0, int nrows, int quad, int tig,
                                         int lane, float acc[8][4]) {
    int row0 = r0 + quad;
    int row1 = row0 + 8;
    bool v0 = row0 < nrows, v1 = row1 < nrows;
    const float2 z2 = make_float2(0.f, 0.f);
    int k0 = 2 * tig;
    float2 c00 = v0 ? *(const float2*)(A + row0 * 128 + k0)     : z2;
    float2 c10 = v1 ? *(const float2*)(A + row1 * 128 + k0)     : z2;
    float2 c01 = v0 ? *(const float2*)(A + row0 * 128 + k0 + 8) : z2;
    float2 c11 = v1 ? *(const float2*)(A + row1 * 128 + k0 + 8) : z2;
#pragma unroll
    for (int ks = 0; ks < 8; ks++) {
        float2 n00, n10, n01, n11;
        if (ks < 7) {
            int kn = (ks + 1) * 16 + 2 * tig;
            n00 = v0 ? *(const float2*)(A + row0 * 128 + kn)     : z2;
            n10 = v1 ? *(const float2*)(A + row1 * 128 + kn)     : z2;
            n01 = v0 ? *(const float2*)(A + row0 * 128 + kn + 8) : z2;
            n11 = v1 ? *(const float2*)(A + row1 * 128 + kn + 8) : z2;
        }
        uint ahi[4], alo[4];
        split2f(c00.x, c00.y, ahi[0], alo[0]);
        split2f(c10.x, c10.y, ahi[1], alo[1]);
        split2f(c01.x, c01.y, ahi[2], alo[2]);
        split2f(c11.x, c11.y, ahi[3], alo[3]);
        const uint4* Fb = Wf_half + ks * 32 + lane;
#pragma unroll
        for (int nt = 0; nt < 8; nt++) {
            uint4 f = __ldg(Fb + nt * 256);
            mma_bf16(acc[nt], ahi, f.x, f.y);    // hi*hi
            mma_bf16(acc[nt], ahi, f.z, f.w);    // hi*lo
            mma_bf16(acc[nt], alo, f.x, f.y);    // lo*hi
        }
        if (ks < 7) { c00 = n00; c10 = n10; c01 = n01; c11 = n11; }
    }
}

// GEMM + conv epilogue: writes raw xw (fp32) AND acc init: 2*dinv^2*xw + b
__global__ void __launch_bounds__(256, 3) k_gemm_conv(const float* __restrict__ A,
                                                      const uint4* __restrict__ Wf,
                                                      const float* __restrict__ bias,
                                                      float* __restrict__ xw_out,
                                                      float* __restrict__ acc_out,
                                                      int nrows) {
    int lane = threadIdx.x & 31;
    int warp = threadIdx.x >> 5;
    int quad = lane >> 2, tig = lane & 3;
    int half = warp & 1;
    int r0 = blockIdx.x * 64 + (warp >> 1) * 16;

    float acc[8][4];
#pragma unroll
    for (int nt = 0; nt < 8; nt++)
#pragma unroll
        for (int c = 0; c < 4; c++) acc[nt][c] = 0.f;

    mma_core(A, Wf + half * 8 * 256, r0, nrows, quad, tig, lane, acc);

    int row0 = r0 + quad, row1 = row0 + 8;
    bool v0 = row0 < nrows, v1 = row1 < nrows;
    float d0 = v0 ? g_dinv[row0] : 0.f;
    float d1 = v1 ? g_dinv[row1] : 0.f;
    float s0 = 2.0f * d0 * d0, s1 = 2.0f * d1 * d1;
#pragma unroll
    for (int nt = 0; nt < 8; nt++) {
        int c = (half * 8 + nt) * 8 + 2 * tig;
        float2 bi = *(const float2*)(bias + c);
        if (v0) {
            *(float2*)(xw_out + row0 * 128 + c)  = make_float2(acc[nt][0], acc[nt][1]);
            *(float2*)(acc_out + row0 * 128 + c) =
                make_float2(s0 * acc[nt][0] + bi.x, s0 * acc[nt][1] + bi.y);
        }
        if (v1) {
            *(float2*)(xw_out + row1 * 128 + c)  = make_float2(acc[nt][2], acc[nt][3]);
            *(float2*)(acc_out + row1 * 128 + c) =
                make_float2(s1 * acc[nt][2] + bi.x, s1 * acc[nt][3] + bi.y);
        }
    }
}

// GEMM applying We2 to agg: h += agg@We2 + attsum*be2
__global__ void __launch_bounds__(256, 3) k_gemm_apply(const float* __restrict__ A,
                                                       const uint4* __restrict__ Wf,
                                                       const float* __restrict__ be2,
                                                       float* __restrict__ h,
                                                       int nrows) {
    int lane = threadIdx.x & 31;
    int warp = threadIdx.x >> 5;
    int quad = lane >> 2, tig = lane & 3;
    int half = warp & 1;
    int r0 = blockIdx.x * 64 + (warp >> 1) * 16;

    float acc[8][4];
#pragma unroll
    for (int nt = 0; nt < 8; nt++)
#pragma unroll
        for (int c = 0; c < 4; c++) acc[nt][c] = 0.f;

    mma_core(A, Wf + half * 8 * 256, r0, nrows, quad, tig, lane, acc);

    int row0 = r0 + quad, row1 = row0 + 8;
    bool v0 = row0 < nrows, v1 = row1 < nrows;
    float as0 = v0 ? g_attsum[row0] : 0.f;
    float as1 = v1 ? g_attsum[row1] : 0.f;
#pragma unroll
    for (int nt = 0; nt < 8; nt++) {
        int c = (half * 8 + nt) * 8 + 2 * tig;
        float2 bi = *(const float2*)(be2 + c);
        if (v0) {
            float2 h0 = *(const float2*)(h + row0 * 128 + c);
            *(float2*)(h + row0 * 128 + c) =
                make_float2(h0.x + acc[nt][0] + as0 * bi.x,
                            h0.y + acc[nt][1] + as0 * bi.y);
        }
        if (v1) {
            float2 h1 = *(const float2*)(h + row1 * 128 + c);
            *(float2*)(h + row1 * 128 + c) =
                make_float2(h1.x + acc[nt][2] + as1 * bi.x,
                            h1.y + acc[nt][3] + as1 * bi.y);
        }
    }
}

// ---------------- conv scatter over dst-sorted edges, run-merged reds --------
__global__ void __launch_bounds__(256) k_conv_scatter(const float* __restrict__ xw,
                                                      float* __restrict__ out) {
    int w = blockIdx.x * 8 + (threadIdx.x >> 5);
    int q = threadIdx.x & 31;
    int base = w * 16;
    float4 acc = make_float4(0.f, 0.f, 0.f, 0.f);
    int cur = __ldg(&g_dstS[base]);
#pragma unroll 4
    for (int i = 0; i < 16; i++) {
        int e = base + i;
        int d = __ldg(&g_dstS[e]);
        if (d != cur) {
            red4(out + cur * 128 + q * 4, acc.x, acc.y, acc.z, acc.w);
            acc = make_float4(0.f, 0.f, 0.f, 0.f);
            cur = d;
        }
        int r = __ldg(&g_srcS[e]);
        float nrm = __ldg(&g_nrmS[e]);
        float4 v = *(const float4*)(xw + r * 128 + q * 4);
        acc.x += nrm * v.x; acc.y += nrm * v.y;
        acc.z += nrm * v.z; acc.w += nrm * v.w;
    }
    red4(out + cur * 128 + q * 4, acc.x, acc.y, acc.z, acc.w);
}

// ---------------- fused elu + attention dots + zero agg buffer ----------------
__global__ void k_elu_att(const float* __restrict__ convAcc, float* __restrict__ h,
                          float* __restrict__ aggZero, const float* __restrict__ Watt) {
    int n    = (blockIdx.x * blockDim.x + threadIdx.x) >> 5;
    int lane = threadIdx.x & 31;
    if (n >= NN) return;
    int base = n * 128 + lane * 4;
    float4 v = *(const float4*)(convAcc + base);
    float4 e4;
    e4.x = eluf(v.x); e4.y = eluf(v.y); e4.z = eluf(v.z); e4.w = eluf(v.w);
    *(float4*)(h + base) = e4;
    *(float4*)(aggZero + base) = make_float4(0.f, 0.f, 0.f, 0.f);
    float4 w1 = *(const float4*)(Watt + lane * 4);
    float4 w2 = *(const float4*)(Watt + 128 + lane * 4);
    float s1 = e4.x * w1.x + e4.y * w1.y + e4.z * w1.z + e4.w * w1.w;
    float s2 = e4.x * w2.x + e4.y * w2.y + e4.z * w2.z + e4.w * w2.w;
#pragma unroll
    for (int o = 16; o > 0; o >>= 1) {
        s1 += __shfl_down_sync(0xffffffffu, s1, o);
        s2 += __shfl_down_sync(0xffffffffu, s2, o);
    }
    if (lane == 0) { g_ar[n] = s1; g_ac[n] = s2; }
}

// ---------------- fused online softmax over E+N logits ----------------
__global__ void k_logit_pass1(const int* __restrict__ ei) {
    const int total = EE + NN;
    int tid = threadIdx.x;
    float m = -1e30f, s = 0.f;
    for (int i = blockIdx.x * blockDim.x + tid; i < total; i += gridDim.x * blockDim.x) {
        int r, c;
        if (i < EE) { r = ei[i]; c = ei[EE + i]; } else { r = c = i - EE; }
        float x = g_ar[r] + g_ac[c];
        if (x <= m) s += expf(x - m);
        else { s = s * expf(m - x) + 1.f; m = x; }
    }
    __shared__ float sm[256], ss[256];
    sm[tid] = m; ss[tid] = s;
    __syncthreads();
    for (int o = 128; o > 0; o >>= 1) {
        if (tid < o) {
            float m2 = sm[tid + o], s2 = ss[tid + o];
            float mm = fmaxf(sm[tid], m2);
            ss[tid] = ss[tid] * expf(sm[tid] - mm) + s2 * expf(m2 - mm);
            sm[tid] = mm;
        }
        __syncthreads();
    }
    if (tid == 0) { g_blockm[blockIdx.x] = sm[0]; g_blocks[blockIdx.x] = ss[0]; }
}

__global__ void k_logit_final() {
    __shared__ float sm[LB], ss[LB];
    int t = threadIdx.x;
    sm[t] = g_blockm[t]; ss[t] = g_blocks[t];
    __syncthreads();
    for (int o = LB / 2; o > 0; o >>= 1) {
        if (t < o) {
            float m2 = sm[t + o], s2 = ss[t + o];
            float mm = fmaxf(sm[t], m2);
            ss[t] = ss[t] * expf(sm[t] - mm) + s2 * expf(m2 - mm);
            sm[t] = mm;
        }
        __syncthreads();
    }
    if (t == 0) { g_gmax = sm[0]; g_invsum = 1.f / ss[0]; }
}

// ---------------- edge MLP (layer 1) via HMMA + weighted hidden scatter -------
#define SH_STRIDE 132
__global__ void __launch_bounds__(256) k_edge_mma_scatter(
        const float* __restrict__ eattr, const int* __restrict__ ei,
        const uint4* __restrict__ Wfe, const float* __restrict__ be1,
        float* __restrict__ agg) {
    __shared__ float sHid[64 * SH_STRIDE];
    __shared__ float sAtt[64];
    __shared__ int   sRow[64];

    int tid  = threadIdx.x;
    int lane = tid & 31;
    int warp = tid >> 5;
    int quad = lane >> 2, tig = lane & 3;
    int half = warp & 1;
    int e0   = blockIdx.x * 64;

    // attention weights for this block's 64 edges (batt cancels in softmax)
    if (tid < 64) {
        int ge = e0 + tid;
        int r = ei[ge], c = ei[EE + ge];
        float at = expf(g_ar[r] + g_ac[c] - g_gmax) * g_invsum;
        sAtt[tid] = at;
        sRow[tid] = r;
        red1(&g_attsum[r], at);
    }

    // MMA: warp computes 16 edges x 64 cols, K=32 (2 k-steps)
    int row0 = (warp >> 1) * 16 + quad;      // local edge row
    int row1 = row0 + 8;
    const float* A = eattr + e0 * 32;
    float acc[8][4];
#pragma unroll
    for (int nt = 0; nt < 8; nt++)
#pragma unroll
        for (int c = 0; c < 4; c++) acc[nt][c] = 0.f;

#pragma unroll
    for (int ks = 0; ks < 2; ks++) {
        int k0 = ks * 16 + 2 * tig;
        float2 f00 = *(const float2*)(A + row0 * 32 + k0);
        float2 f10 = *(const float2*)(A + row1 * 32 + k0);
        float2 f01 = *(const float2*)(A + row0 * 32 + k0 + 8);
        float2 f11 = *(const float2*)(A + row1 * 32 + k0 + 8);
        uint ahi[4], alo[4];
        split2f(f00.x, f00.y, ahi[0], alo[0]);
        split2f(f10.x, f10.y, ahi[1], alo[1]);
        split2f(f01.x, f01.y, ahi[2], alo[2]);
        split2f(f11.x, f11.y, ahi[3], alo[3]);
        const uint4* Fb = Wfe + (half * 8) * 64 + ks * 32 + lane;
#pragma unroll
        for (int nt = 0; nt < 8; nt++) {
            uint4 f = __ldg(Fb + nt * 64);
            mma_bf16(acc[nt], ahi, f.x, f.y);    // hi*hi
            mma_bf16(acc[nt], ahi, f.z, f.w);    // hi*lo
            mma_bf16(acc[nt], alo, f.x, f.y);    // lo*hi
        }
    }

    // stage relu(acc + be1) into smem
#pragma unroll
    for (int nt = 0; nt < 8; nt++) {
        int c = (half * 8 + nt) * 8 + 2 * tig;
        float2 bi = *(const float2*)(be1 + c);
        sHid[row0 * SH_STRIDE + c]     = fmaxf(acc[nt][0] + bi.x, 0.f);
        sHid[row0 * SH_STRIDE + c + 1] = fmaxf(acc[nt][1] + bi.y, 0.f);
        sHid[row1 * SH_STRIDE + c]     = fmaxf(acc[nt][2] + bi.x, 0.f);
        sHid[row1 * SH_STRIDE + c + 1] = fmaxf(acc[nt][3] + bi.y, 0.f);
    }
    __syncthreads();

    // scatter: agg[row[e]] += att[e]*hidden
    int ce = tid & 15;
    int re = tid >> 4;
#pragma unroll
    for (int r = 0; r < 4; r++) {
        int le = re * 4 + r;
        float at = sAtt[le];
        const float* hp = sHid + le * SH_STRIDE + ce * 8;
        float* dst = agg + sRow[le] * 128 + ce * 8;
        red4(dst,     at * hp[0], at * hp[1], at * hp[2], at * hp[3]);
        red4(dst + 4, at * hp[4], at * hp[5], at * hp[6], at * hp[7]);
    }
}

// ---------------- pooling + fc ----------------
__global__ void k_elu_pool(const float* __restrict__ outC, const int* __restrict__ batch) {
    int n    = (blockIdx.x * blockDim.x + threadIdx.x) >> 5;
    int lane = threadIdx.x & 31;
    if (n >= NN) return;
    int base = n * 128 + lane * 4;
    float4 v = *(const float4*)(outC + base);
    int g = __ldg(&batch[n]);
    red4(&g_pooled[g * 128 + lane * 4], eluf(v.x), eluf(v.y), eluf(v.z), eluf(v.w));
}

__global__ void k_fc(const float* __restrict__ Wfc, const float* __restrict__ bfc,
                     float* __restrict__ out) {
    int g = threadIdx.x;
    if (g >= GG) return;
    float s = 0.f;
#pragma unroll
    for (int j = 0; j < 128; j++) s += g_pooled[g * 128 + j] * Wfc[j];
    out[g] = s / fmaxf(g_cnt[g], 1.0f) + bfc[0];
}

// ---------------- launch ----------------
extern "C" void kernel_launch(void* const* d_in, const int* in_sizes, int n_in,
                              void* d_out, int out_size) {
    const float* x     = (const float*)d_in[0];
    const int*   ei    = (const int*)d_in[1];
    const float* eattr = (const float*)d_in[2];
    const int*   batch = (const int*)d_in[3];
    const float* W1    = (const float*)d_in[4];
    const float* b1    = (const float*)d_in[5];
    const float* W2    = (const float*)d_in[6];
    const float* b2    = (const float*)d_in[7];
    const float* We1   = (const float*)d_in[8];
    const float* be1   = (const float*)d_in[9];
    const float* We2   = (const float*)d_in[10];
    const float* be2   = (const float*)d_in[11];
    const float* Watt  = (const float*)d_in[12];
    const float* Wfc   = (const float*)d_in[14];
    const float* bfc   = (const float*)d_in[15];
    float* out = (float*)d_out;

    float *bufA, *bufB, *bufC;
    uint4 *wf1, *wf2, *wfa, *wfe;
    cudaGetSymbolAddress((void**)&bufA, g_bufA);
    cudaGetSymbolAddress((void**)&bufB, g_bufB);
    cudaGetSymbolAddress((void**)&bufC, g_bufC);
    cudaGetSymbolAddress((void**)&wf1, g_wf1);
    cudaGetSymbolAddress((void**)&wf2, g_wf2);
    cudaGetSymbolAddress((void**)&wfa, g_wfa);
    cudaGetSymbolAddress((void**)&wfe, g_wfe);

    // side stream + fork/join events (created once; graph-capture fork pattern)
    static cudaStream_t s2 = nullptr;
    static cudaEvent_t  eFork = nullptr, eJoin = nullptr;
    if (!s2) {
        cudaStreamCreateWithFlags(&s2, cudaStreamNonBlocking);
        cudaEventCreateWithFlags(&eFork, cudaEventDisableTiming);
        cudaEventCreateWithFlags(&eJoin, cudaEventDisableTiming);
    }

    const int T = 256;

    k_init<<<(NN + T - 1) / T, T>>>(W1, W2, We2, We1);
    k_count<<<(EE + T - 1) / T, T>>>(ei);
    k_scan<<<1, SCAN_T>>>();

    // fork: fill + cnt run on s2 concurrently with conv1 GEMM on main
    cudaEventRecord(eFork, 0);
    cudaStreamWaitEvent(s2, eFork, 0);
    k_fill<<<(EE + T - 1) / T, T, 0, s2>>>(ei);
    k_cnt<<<(NN / (T * 8)) + 1, T, 0, s2>>>(batch);
    cudaEventRecord(eJoin, s2);

    // conv1 GEMM (tensor cores) on main stream
    k_gemm_conv<<<(NN + 63) / 64, 256>>>(x, wf1, b1, bufA, bufC, NN);

    // join: scatter needs both the GEMM output and the sorted edge arrays
    cudaStreamWaitEvent(0, eJoin, 0);
    k_conv_scatter<<<EE / 128, 256>>>(bufA, bufC);

    // h = elu(conv1); attention dots; zero agg buffer (bufC)
    k_elu_att<<<(NN * 32 + T - 1) / T, T>>>(bufC, bufB, bufC, Watt);

    // global online softmax over E+N logits
    k_logit_pass1<<<LB, 256>>>(ei);
    k_logit_final<<<1, LB>>>();

    // edge MLP layer1 (HMMA) + att-weighted scatter of hidden into bufC
    k_edge_mma_scatter<<<EE / 64, 256>>>(eattr, ei, wfe, be1, bufC);

    // node-side We2: h += agg@We2 + attsum*be2
    k_gemm_apply<<<(NN + 63) / 64, 256>>>(bufC, wfa, be2, bufB, NN);

    // conv2
    k_gemm_conv<<<(NN + 63) / 64, 256>>>(bufB, wf2, b2, bufA, bufC, NN);
    k_conv_scatter<<<EE / 128, 256>>>(bufA, bufC);

    // elu + global mean pool + fc
    k_elu_pool<<<(NN * 32 + T - 1) / T, T>>>(bufC, batch);
    k_fc<<<1, 64>>>(Wfc, bfc, out);
}